// round 4
// baseline (speedup 1.0000x reference)
#include <cuda_runtime.h>

#define NCLS 80
#define NB 16
#define NQ 300
#define NT 50
#define HDIM 128
#define HM_BLOCKS 1184
#define THREADS 256
#define NPAIR (NB * NT)   // 800
#define HSLOTS 2048

// global accumulators (zeroed at module load; k_rest re-zeros them at the end
// of every invocation so graph replays stay deterministic)
__device__ double g_hm  = 0.0;
__device__ double g_cen = 0.0;
__device__ double g_ced = 0.0;

// focal loss term for target==0, WITHOUT the 0.75 alpha factor:
//   softplus(x) * sigmoid(x)^2
__device__ __forceinline__ float focal_neg(float x) {
    float t   = __expf(-fabsf(x));           // MUFU
    float omp = 1.0f + t;
    float r   = __fdividef(1.0f, omp);       // MUFU rcp
    float L   = __logf(omp);                 // MUFU  (= log1p(t))
    float sp  = fmaxf(x, 0.0f) + L;          // softplus(x)
    float s   = (x >= 0.0f ? 1.0f : t) * r;  // sigmoid(x)
    return sp * s * s;
}

// (alpha-weighted positive term) - (alpha-weighted negative term) at a
// positive cell, accurate-math version (only ~800 calls)
__device__ __forceinline__ float focal_delta(float x) {
    float t   = expf(-fabsf(x));
    float L   = log1pf(t);
    float omp = 1.0f + t;
    float sig = (x >= 0.0f ? 1.0f : t) / omp;       // sigmoid(x)
    float sp_neg = fmaxf(x, 0.0f) + L;              // softplus(x)
    float sp_pos = fmaxf(-x, 0.0f) + L;             // softplus(-x)
    float pos = 0.25f * sp_pos * (1.0f - sig) * (1.0f - sig);
    float neg = 0.75f * sp_neg * sig * sig;
    return pos - neg;
}

// ---------------------------------------------------------------------------
// Kernel 1: fused dense heatmap focal base sum (blocks [0, HM_BLOCKS)) and
// classification cross-entropy (blocks [HM_BLOCKS, HM_BLOCKS+NB))
// ---------------------------------------------------------------------------
__global__ void k_main(const float4* __restrict__ hm4, long nvec,
                       const float* __restrict__ logits,
                       const int*   __restrict__ src_idx,
                       const int*   __restrict__ tgt_idx,
                       const int*   __restrict__ tgt_labels,
                       const float* __restrict__ ew)
{
    int tid = threadIdx.x;
    if (blockIdx.x < HM_BLOCKS) {
        // ---- dense focal(target=0) over the heatmap ----
        float acc = 0.0f;
        long stride = (long)HM_BLOCKS * THREADS;
        long i = (long)blockIdx.x * THREADS + tid;
        #pragma unroll 4
        for (; i < nvec; i += stride) {
            float4 v = hm4[i];
            acc += focal_neg(v.x);
            acc += focal_neg(v.y);
            acc += focal_neg(v.z);
            acc += focal_neg(v.w);
        }
        #pragma unroll
        for (int o = 16; o; o >>= 1) acc += __shfl_xor_sync(0xffffffffu, acc, o);
        __shared__ float sred[THREADS / 32];
        if ((tid & 31) == 0) sred[tid >> 5] = acc;
        __syncthreads();
        if (tid == 0) {
            double s = 0.0;
            for (int w = 0; w < THREADS / 32; w++) s += (double)sred[w];
            atomicAdd(&g_hm, 0.75 * s);
        }
    } else {
        // ---- CE: one block per batch ----
        int b = blockIdx.x - HM_BLOCKS;
        __shared__ int tcls[NQ];
        for (int q = tid; q < NQ; q += THREADS) tcls[q] = NCLS;
        __syncthreads();
        if (tid < NT) {
            int si = src_idx[b * NT + tid];
            int ti = tgt_idx[b * NT + tid];
            tcls[si] = tgt_labels[b * NT + ti];
        }
        __syncthreads();
        int warp = tid >> 5, lane = tid & 31;
        float an = 0.0f, ad = 0.0f;
        for (int q = warp; q < NQ; q += THREADS / 32) {
            const float* row = logits + (long)(b * NQ + q) * (NCLS + 1);
            float v0 = row[lane];
            float v1 = row[lane + 32];
            float v2 = (lane < 17) ? row[lane + 64] : -1e30f;
            float m = fmaxf(fmaxf(v0, v1), v2);
            #pragma unroll
            for (int o = 16; o; o >>= 1) m = fmaxf(m, __shfl_xor_sync(0xffffffffu, m, o));
            float s = __expf(v0 - m) + __expf(v1 - m) + ((lane < 17) ? __expf(v2 - m) : 0.0f);
            #pragma unroll
            for (int o = 16; o; o >>= 1) s += __shfl_xor_sync(0xffffffffu, s, o);
            if (lane == 0) {
                int c = tcls[q];
                float nll = m + __logf(s) - row[c];
                float w = ew[c];
                an += w * nll;
                ad += w;
            }
        }
        __shared__ float sn[THREADS / 32], sd[THREADS / 32];
        if (lane == 0) { sn[warp] = an; sd[warp] = ad; }
        __syncthreads();
        if (tid == 0) {
            double n = 0.0, d = 0.0;
            for (int w = 0; w < THREADS / 32; w++) { n += (double)sn[w]; d += (double)sd[w]; }
            atomicAdd(&g_cen, n);
            atomicAdd(&g_ced, d);
        }
    }
}

// ---------------------------------------------------------------------------
// Kernel 2 (single block): matched-pair L1 + GIoU, sparse positives dedup via
// shared hash tables, aux focal/box corrections, finalize, reset accumulators.
// ---------------------------------------------------------------------------
__global__ void k_rest(const float* __restrict__ pred_boxes,
                       const float* __restrict__ tgt_boxes,
                       const float* __restrict__ tgt_sizes,
                       const int*   __restrict__ src_idx,
                       const int*   __restrict__ tgt_idx,
                       const int*   __restrict__ tgt_labels,
                       const float* __restrict__ heatmap,
                       const float* __restrict__ box_map,
                       float* __restrict__ out)
{
    __shared__ int pk[HSLOTS], pmin[HSLOTS], pmax[HSLOTS];  // pos cells (b,gy,gx)
    __shared__ int gk[HSLOTS], gmin[HSLOTS];                // heatmap cells (b,lf,gy,gx)
    __shared__ float s_l1, s_gi, s_bc, s_hc;
    __shared__ int s_np;
    int tid = threadIdx.x;
    for (int i = tid; i < HSLOTS; i += blockDim.x) {
        pk[i] = -1; pmin[i] = 0x7fffffff; pmax[i] = -1;
        gk[i] = -1; gmin[i] = 0x7fffffff;
    }
    if (tid == 0) { s_l1 = 0.f; s_gi = 0.f; s_bc = 0.f; s_hc = 0.f; s_np = 0; }
    __syncthreads();

    bool act = tid < NPAIR;
    int b = tid / NT;
    float l1 = 0.f, gi = 0.f, bc = 0.f, hc = 0.f;
    int npc = 0;
    int pslot = -1, gslot = -1;
    float bfv[4];
    int gx = 0, gy = 0, lf = 0;

    if (act) {
        float iw = 1.0f / tgt_sizes[b * 2 + 1];  // w_im = sizes[:,1]
        float ih = 1.0f / tgt_sizes[b * 2 + 0];  // h_im = sizes[:,0]

        // ---- matched pair losses ----
        int si = src_idx[tid];
        int ti = tgt_idx[tid];
        const float* sb = pred_boxes + (long)(b * NQ + si) * 4;
        float scx = sb[0], scy = sb[1], sw = sb[2], sh = sb[3];
        const float* tb = tgt_boxes + (long)(b * NT + ti) * 4;
        float tx1 = tb[0] * iw, ty1 = tb[1] * ih, tx2 = tb[2] * iw, ty2 = tb[3] * ih;
        float tcx = (tx1 + tx2) * 0.5f, tcy = (ty1 + ty2) * 0.5f;
        float tw = tx2 - tx1, th = ty2 - ty1;
        l1 = fabsf(scx - tcx) + fabsf(scy - tcy) + fabsf(sw - tw) + fabsf(sh - th);

        float ax1 = scx - 0.5f * sw, ay1 = scy - 0.5f * sh;
        float ax2 = scx + 0.5f * sw, ay2 = scy + 0.5f * sh;
        float bx1 = tcx - 0.5f * tw, by1 = tcy - 0.5f * th;
        float bx2 = tcx + 0.5f * tw, by2 = tcy + 0.5f * th;
        float aa = (ax2 - ax1) * (ay2 - ay1);
        float ab = (bx2 - bx1) * (by2 - by1);
        float wi = fmaxf(fminf(ax2, bx2) - fmaxf(ax1, bx1), 0.f);
        float hi = fmaxf(fminf(ay2, by2) - fmaxf(ay1, by1), 0.f);
        float inter = wi * hi;
        float uni = aa + ab - inter;
        float iou = inter / uni;
        float cw = fmaxf(fmaxf(ax2, bx2) - fminf(ax1, bx1), 0.f);
        float ch = fmaxf(fmaxf(ay2, by2) - fminf(ay1, by1), 0.f);
        float ac = cw * ch;
        gi = 1.0f - (iou - (ac - uni) / ac);

        // ---- aux positives use ORIGINAL target order ----
        const float* ob = tgt_boxes + (long)tid * 4;
        float ox1 = ob[0] * iw, oy1 = ob[1] * ih, ox2 = ob[2] * iw, oy2 = ob[3] * ih;
        bfv[0] = (ox1 + ox2) * 0.5f;
        bfv[1] = (oy1 + oy2) * 0.5f;
        bfv[2] = ox2 - ox1;
        bfv[3] = oy2 - oy1;
        gx = min(max((int)(bfv[0] * (float)HDIM), 0), HDIM - 1);
        gy = min(max((int)(bfv[1] * (float)HDIM), 0), HDIM - 1);
        lf = tgt_labels[tid];

        int kp = (b << 14) | (gy << 7) | gx;
        int kg = (b << 21) | (lf << 14) | (gy << 7) | gx;

        // pos table: first occurrence -> num_pos; last occurrence -> box owner
        int slot = (int)(((unsigned)kp * 2654435761u) >> 11) & (HSLOTS - 1);
        while (true) {
            int old = atomicCAS(&pk[slot], -1, kp);
            if (old == -1 || old == kp) {
                atomicMin(&pmin[slot], tid);
                atomicMax(&pmax[slot], tid);
                pslot = slot;
                break;
            }
            slot = (slot + 1) & (HSLOTS - 1);
        }
        // heatmap table: first occurrence -> focal correction
        slot = (int)(((unsigned)kg * 2654435761u) >> 11) & (HSLOTS - 1);
        while (true) {
            int old = atomicCAS(&gk[slot], -1, kg);
            if (old == -1 || old == kg) {
                atomicMin(&gmin[slot], tid);
                gslot = slot;
                break;
            }
            slot = (slot + 1) & (HSLOTS - 1);
        }
    }
    __syncthreads();

    if (act) {
        if (pmin[pslot] == tid) npc = 1;
        if (pmax[pslot] == tid) {  // last write wins for box_target
            #pragma unroll
            for (int c = 0; c < 4; c++) {
                float bm = box_map[(((long)b * 4 + c) * HDIM + gy) * HDIM + gx];
                bc += fabsf(bm - bfv[c]);
            }
        }
        if (gmin[gslot] == tid) {  // distinct positive heatmap cell
            float x = heatmap[(((long)b * NCLS + lf) * HDIM + gy) * HDIM + gx];
            hc = focal_delta(x);
        }
    }

    // block reduce (warp shuffle + lane0 shared atomics)
    #pragma unroll
    for (int o = 16; o; o >>= 1) {
        l1  += __shfl_xor_sync(0xffffffffu, l1, o);
        gi  += __shfl_xor_sync(0xffffffffu, gi, o);
        bc  += __shfl_xor_sync(0xffffffffu, bc, o);
        hc  += __shfl_xor_sync(0xffffffffu, hc, o);
        npc += __shfl_xor_sync(0xffffffffu, npc, o);
    }
    if ((tid & 31) == 0) {
        atomicAdd(&s_l1, l1);
        atomicAdd(&s_gi, gi);
        atomicAdd(&s_bc, bc);
        atomicAdd(&s_hc, hc);
        atomicAdd(&s_np, npc);
    }
    __syncthreads();

    if (tid == 0) {
        double cen = g_cen, ced = g_ced, hmb = g_hm;
        g_cen = 0.0; g_ced = 0.0; g_hm = 0.0;   // reset for next graph replay
        double ce   = cen / ced;
        double bbox = (double)s_l1 / (double)NPAIR;
        double giou = (double)s_gi / (double)NPAIR;
        double np   = (double)(s_np > 0 ? s_np : 1);
        double hml  = (hmb + (double)s_hc) / np;
        double bxl  = (double)s_bc / np;
        double aux  = hml + 5.0 * bxl;
        out[0] = (float)ce;
        out[1] = (float)bbox;
        out[2] = (float)giou;
        out[3] = (float)aux;
        out[4] = (float)(1.0 * ce + 5.0 * bbox + 2.0 * giou + 1.0 * aux);
    }
}

extern "C" void kernel_launch(void* const* d_in, const int* in_sizes, int n_in,
                              void* d_out, int out_size)
{
    const float* pred_logits  = (const float*)d_in[0];
    const float* pred_boxes   = (const float*)d_in[1];
    const float* heatmap      = (const float*)d_in[2];
    const float* box_map      = (const float*)d_in[3];
    const float* tgt_boxes    = (const float*)d_in[4];
    const int*   tgt_labels   = (const int*)d_in[5];
    const float* tgt_sizes    = (const float*)d_in[6];
    const int*   src_idx      = (const int*)d_in[7];
    const int*   tgt_idx      = (const int*)d_in[8];
    const float* empty_weight = (const float*)d_in[9];
    float* out = (float*)d_out;

    long nvec = (long)in_sizes[2] / 4;  // heatmap element count / 4 (float4)

    k_main<<<HM_BLOCKS + NB, THREADS>>>((const float4*)heatmap, nvec,
                                        pred_logits, src_idx, tgt_idx,
                                        tgt_labels, empty_weight);
    k_rest<<<1, 1024>>>(pred_boxes, tgt_boxes, tgt_sizes,
                        src_idx, tgt_idx, tgt_labels,
                        heatmap, box_map, out);
}